// round 10
// baseline (speedup 1.0000x reference)
#include <cuda_runtime.h>

#define T_STEPS 2000
#define N_IN    8192
#define N_OUT   4096

// 32 MB scratch for lif_input = x @ W^T  (allocation-free: __device__ global)
__device__ float g_lif[(size_t)T_STEPS * N_OUT];
__device__ int   g_flags[16];

constexpr int BM = 128, BN = 128, BK = 8, TM = 8, TN = 8;
constexpr int N_BLK = N_OUT / BN;     // 32 tiles per m-block
constexpr int M_BLK = 16;             // ceil(2000/128)

__global__ void zero_flags_kernel() {
    if (threadIdx.x < M_BLK) g_flags[threadIdx.x] = 0;
}

__device__ __forceinline__ int ld_acquire_gpu(const int* p) {
    int v;
    asm volatile("ld.acquire.gpu.s32 %0, [%1];" : "=r"(v) : "l"(p) : "memory");
    return v;
}

// branch-free LIF step (values identical to the rel_err-0.0 R8 version)
__device__ __forceinline__ float lif_step(float inp, float& v, float& refrac,
                                          float dt_tau, float rest, float th,
                                          float rst, float trf)
{
    const float DT = 0.001f;
    float v1 = v - dt_tau * (v - rest);
    float va = v1 + inp;
    v1 = (refrac == 0.0f) ? va : v1;
    float rf = refrac - DT;
    rf = (refrac > 0.0f) ? rf : 0.0f;
    float spike = (v1 - th >= 0.0f) ? 1.0f : 0.0f;
    bool sb = (spike > 0.0f);
    refrac = sb ? trf : rf;
    v = sb ? rst : v1;
    return spike;
}

// ---------------------------------------------------------------------------
// One kernel, grid = 512 GEMM tiles. Every CTA computes its tile (math
// byte-identical to R1's pipe-saturated SGEMM), signals its m-block flag,
// and then CTAs 0..15 switch roles and run the LIF scan, consuming m-blocks
// as they complete. No extra CTAs -> wave count identical to R1.
// ---------------------------------------------------------------------------
__global__ __launch_bounds__(256, 2)
void fused_gemm_scan_kernel(const float* __restrict__ A,   // x [M, K]
                            const float* __restrict__ B,   // w [N, K]
                            const float* __restrict__ v_th,
                            const float* __restrict__ v_rest,
                            const float* __restrict__ v_reset,
                            const float* __restrict__ t_ref,
                            const float* __restrict__ tau,
                            float* __restrict__ out,
                            int M, int N, int K)
{
    __shared__ float As[BK][BM];
    __shared__ float Bs[BK][BN];

    const int bid = blockIdx.x;
    const int tid = threadIdx.x;

    // =================== GEMM phase (bit-exact R1) ===================
    {
        const int mb = bid >> 5;            // 0..15 (low bids -> m-block 0 first)
        const int bm = mb * BM;
        const int bn = (bid & 31) * BN;
        float* C = g_lif;

        const int loadRow = tid >> 1;
        const int loadCol = (tid & 1) * 4;
        const int tr = (tid >> 4) * TM;
        const int tc = (tid & 15) * TN;

        float acc[TM][TN];
        #pragma unroll
        for (int i = 0; i < TM; i++)
            #pragma unroll
            for (int j = 0; j < TN; j++)
                acc[i][j] = 0.0f;

        const bool aValid = (bm + loadRow) < M;
        const float* Aptr = A + (size_t)(bm + loadRow) * K + loadCol;
        const float* Bptr = B + (size_t)(bn + loadRow) * K + loadCol;

        for (int k0 = 0; k0 < K; k0 += BK) {
            float4 a4 = aValid ? *(const float4*)(Aptr + k0)
                               : make_float4(0.f, 0.f, 0.f, 0.f);
            float4 b4 = *(const float4*)(Bptr + k0);

            As[loadCol + 0][loadRow] = a4.x;
            As[loadCol + 1][loadRow] = a4.y;
            As[loadCol + 2][loadRow] = a4.z;
            As[loadCol + 3][loadRow] = a4.w;
            Bs[loadCol + 0][loadRow] = b4.x;
            Bs[loadCol + 1][loadRow] = b4.y;
            Bs[loadCol + 2][loadRow] = b4.z;
            Bs[loadCol + 3][loadRow] = b4.w;
            __syncthreads();

            #pragma unroll
            for (int k = 0; k < BK; k++) {
                float ar[TM], br[TN];
                #pragma unroll
                for (int i = 0; i < TM; i++) ar[i] = As[k][tr + i];
                #pragma unroll
                for (int j = 0; j < TN; j++) br[j] = Bs[k][tc + j];
                #pragma unroll
                for (int i = 0; i < TM; i++)
                    #pragma unroll
                    for (int j = 0; j < TN; j++)
                        acc[i][j] += ar[i] * br[j];   // ascending-k fma chain
            }
            __syncthreads();
        }

        #pragma unroll
        for (int i = 0; i < TM; i++) {
            int gm = bm + tr + i;
            if (gm < M) {
                float* Crow = C + (size_t)gm * N + bn + tc;
                #pragma unroll
                for (int j = 0; j < TN; j += 4) {
                    float4 v = make_float4(acc[i][j], acc[i][j+1],
                                           acc[i][j+2], acc[i][j+3]);
                    *(float4*)(Crow + j) = v;
                }
            }
        }

        __threadfence();
        __syncthreads();
        if (tid == 0) atomicAdd(&g_flags[mb], 1);
    }

    // =================== scan phase (CTAs 0..15 only) ===================
    if (bid >= 16) return;

    const int n = bid * 256 + tid;          // 16 * 256 = 4096 neurons

    const float th   = v_th[n];
    const float rest = v_rest[n];
    const float rst  = v_reset[n];
    const float trf  = t_ref[n];
    const float dt_tau = 0.001f * tau[n];

    float v = rest;
    float refrac = 0.0f;
    out[n] = 0.0f;                          // s[0] = 0

    const float* lif = g_lif;

    for (int b = 0; b < M_BLK; b++) {
        const int t0 = (b == 0) ? 1 : b * BM;
        const int t1 = (b + 1) * BM < T_STEPS ? (b + 1) * BM : T_STEPS;

        // wait for all 32 n-tiles of m-block b
        if (tid == 0) {
            while (ld_acquire_gpu(&g_flags[b]) < N_BLK) __nanosleep(128);
        }
        __syncthreads();

        int t = t0;
        // full 16-step batches with prefetch
        while (t + 16 <= t1) {
            float buf[16];
            #pragma unroll
            for (int j = 0; j < 16; j++)
                buf[j] = lif[(size_t)(t + j) * N_OUT + n];
            #pragma unroll
            for (int j = 0; j < 16; j++)
                out[(size_t)(t + j) * N_OUT + n] =
                    lif_step(buf[j], v, refrac, dt_tau, rest, th, rst, trf);
            t += 16;
        }
        // remainder (only for b==0: 15 steps, b==15: 80 -> 0 after batches)
        while (t < t1) {
            float inp = lif[(size_t)t * N_OUT + n];
            out[(size_t)t * N_OUT + n] =
                lif_step(inp, v, refrac, dt_tau, rest, th, rst, trf);
            t++;
        }
    }
}

// ---------------------------------------------------------------------------
extern "C" void kernel_launch(void* const* d_in, const int* in_sizes, int n_in,
                              void* d_out, int out_size)
{
    const float* x       = (const float*)d_in[0];  // [T, N_IN]
    const float* weight  = (const float*)d_in[1];  // [N_OUT, N_IN]
    const float* v_th    = (const float*)d_in[2];
    const float* v_rest  = (const float*)d_in[3];
    const float* v_reset = (const float*)d_in[4];
    const float* t_ref   = (const float*)d_in[5];
    const float* tau     = (const float*)d_in[6];
    float* out = (float*)d_out;                    // [T, N_OUT]

    zero_flags_kernel<<<1, 32>>>();

    const int grid = M_BLK * N_BLK;   // 512 — identical wave structure to R1
    fused_gemm_scan_kernel<<<grid, 256>>>(x, weight,
                                          v_th, v_rest, v_reset, t_ref, tau,
                                          out, T_STEPS, N_OUT, N_IN);
}

// round 11
// speedup vs baseline: 1.0640x; 1.0640x over previous
#include <cuda_runtime.h>

#define T_STEPS 2000
#define N_IN    8192
#define N_OUT   4096

// 32 MB scratch for lif_input = x @ W^T  (allocation-free: __device__ global)
__device__ float g_lif[(size_t)T_STEPS * N_OUT];

// ---------------------------------------------------------------------------
// Phase 1: fp32 GEMM, BM=80 so 25 blocks cover M=2000 EXACTLY (no padded-row
// FLOPs). Per-output math: ascending-k fp32 fma chain — identical to R1.
// 320 threads, micro-tile 8m x 4n, occupancy 2.
// ---------------------------------------------------------------------------
constexpr int BM = 80, BN = 128, BK = 8, TM = 8, TN = 4;

__global__ __launch_bounds__(320)
void gemm_nt_kernel(const float* __restrict__ A,   // [M,K]  M = 2000
                    const float* __restrict__ B,   // [N,K]
                    float* __restrict__ C,         // [M,N]
                    int K)
{
    __shared__ float As[BK][BM];   // 2.5 KB
    __shared__ float Bs[BK][BN];   // 4 KB

    const int tid = threadIdx.x;
    const int bm  = blockIdx.y * BM;   // 0..1920, +80 -> never exceeds 2000
    const int bn  = blockIdx.x * BN;

    // compute mapping: warp w owns m-rows [8w, 8w+8); lane owns n-cols 4*lane
    const int tr = (tid >> 5) * TM;    // 0..72  (10 warps)
    const int tc = (tid & 31) * TN;    // 0..124

    // A loader: 80 rows x 8k = 160 float4 (threads 0..159)
    const int aRow = tid >> 1;
    const int aCol = (tid & 1) * 4;
    // B loader: 128 rows x 8k = 256 float4 (threads 0..255)
    const int bRow = tid >> 1;
    const int bCol = (tid & 1) * 4;

    float acc[TM][TN];
    #pragma unroll
    for (int i = 0; i < TM; i++)
        #pragma unroll
        for (int j = 0; j < TN; j++)
            acc[i][j] = 0.0f;

    const float* Aptr = A + (size_t)(bm + aRow) * K + aCol;
    const float* Bptr = B + (size_t)(bn + bRow) * K + bCol;

    for (int k0 = 0; k0 < K; k0 += BK) {
        if (tid < 160) {
            float4 a4 = *(const float4*)(Aptr + k0);
            As[aCol + 0][aRow] = a4.x;
            As[aCol + 1][aRow] = a4.y;
            As[aCol + 2][aRow] = a4.z;
            As[aCol + 3][aRow] = a4.w;
        }
        if (tid < 256) {
            float4 b4 = *(const float4*)(Bptr + k0);
            Bs[bCol + 0][bRow] = b4.x;
            Bs[bCol + 1][bRow] = b4.y;
            Bs[bCol + 2][bRow] = b4.z;
            Bs[bCol + 3][bRow] = b4.w;
        }
        __syncthreads();

        #pragma unroll
        for (int k = 0; k < BK; k++) {
            float ar[TM], br[TN];
            #pragma unroll
            for (int i = 0; i < TM; i++) ar[i] = As[k][tr + i];   // warp-broadcast
            #pragma unroll
            for (int j = 0; j < TN; j++) br[j] = Bs[k][tc + j];   // 16B/lane
            #pragma unroll
            for (int i = 0; i < TM; i++)
                #pragma unroll
                for (int j = 0; j < TN; j++)
                    acc[i][j] += ar[i] * br[j];   // ascending-k fma chain
        }
        __syncthreads();
    }

    // epilogue: every row < 2000 by construction
    #pragma unroll
    for (int i = 0; i < TM; i++) {
        const int gm = bm + tr + i;
        float4 v = make_float4(acc[i][0], acc[i][1], acc[i][2], acc[i][3]);
        *(float4*)(C + (size_t)gm * N_OUT + bn + tc) = v;
    }
}

// ---------------------------------------------------------------------------
// Phase 2: LIF scan — unchanged from R8 (91 us, rel_err 0.0)
// ---------------------------------------------------------------------------
constexpr int PF = 16;          // 1999 = 16 (prime) + 123*16 + 15 (tail)
constexpr int NBATCH = 123;
constexpr int TAIL = 15;

__device__ __forceinline__ float lif_step(float inp, float& v, float& refrac,
                                          float dt_tau, float rest, float th,
                                          float rst, float trf)
{
    const float DT = 0.001f;
    float v1 = v - dt_tau * (v - rest);
    float va = v1 + inp;
    v1 = (refrac == 0.0f) ? va : v1;
    float rf = refrac - DT;
    rf = (refrac > 0.0f) ? rf : 0.0f;
    float spike = (v1 - th >= 0.0f) ? 1.0f : 0.0f;
    bool sb = (spike > 0.0f);
    refrac = sb ? trf : rf;
    v = sb ? rst : v1;
    return spike;
}

__global__ __launch_bounds__(32)
void lif_scan_kernel(const float* __restrict__ lif,
                     float* __restrict__ out,
                     const float* __restrict__ v_th,
                     const float* __restrict__ v_rest,
                     const float* __restrict__ v_reset,
                     const float* __restrict__ t_ref,
                     const float* __restrict__ tau)
{
    const int n = blockIdx.x * 32 + threadIdx.x;

    const float th   = v_th[n];
    const float rest = v_rest[n];
    const float rst  = v_reset[n];
    const float trf  = t_ref[n];
    const float dt_tau = 0.001f * tau[n];

    float v = rest;
    float refrac = 0.0f;
    out[n] = 0.0f;

    const float* p = lif + (size_t)1 * N_OUT + n;
    float*       q = out + (size_t)1 * N_OUT + n;

    float buf[PF];
    #pragma unroll
    for (int j = 0; j < PF; j++) buf[j] = p[(size_t)j * N_OUT];
    p += (size_t)PF * N_OUT;

    for (int b = 0; b < NBATCH; b++) {
        float cur[PF];
        #pragma unroll
        for (int j = 0; j < PF; j++) cur[j] = buf[j];
        #pragma unroll
        for (int j = 0; j < PF; j++) buf[j] = p[(size_t)j * N_OUT];
        p += (size_t)PF * N_OUT;
        #pragma unroll
        for (int j = 0; j < PF; j++)
            q[(size_t)j * N_OUT] =
                lif_step(cur[j], v, refrac, dt_tau, rest, th, rst, trf);
        q += (size_t)PF * N_OUT;
    }

    {
        float tail[TAIL];
        #pragma unroll
        for (int j = 0; j < TAIL; j++) tail[j] = p[(size_t)j * N_OUT];
        #pragma unroll
        for (int j = 0; j < PF; j++)
            q[(size_t)j * N_OUT] =
                lif_step(buf[j], v, refrac, dt_tau, rest, th, rst, trf);
        q += (size_t)PF * N_OUT;
        #pragma unroll
        for (int j = 0; j < TAIL; j++)
            q[(size_t)j * N_OUT] =
                lif_step(tail[j], v, refrac, dt_tau, rest, th, rst, trf);
    }
}

// ---------------------------------------------------------------------------
extern "C" void kernel_launch(void* const* d_in, const int* in_sizes, int n_in,
                              void* d_out, int out_size)
{
    const float* x       = (const float*)d_in[0];  // [T, N_IN]
    const float* weight  = (const float*)d_in[1];  // [N_OUT, N_IN]
    const float* v_th    = (const float*)d_in[2];
    const float* v_rest  = (const float*)d_in[3];
    const float* v_reset = (const float*)d_in[4];
    const float* t_ref   = (const float*)d_in[5];
    const float* tau     = (const float*)d_in[6];
    float* out = (float*)d_out;                    // [T, N_OUT]

    float* lif_ptr = nullptr;
    cudaGetSymbolAddress((void**)&lif_ptr, g_lif);

    // GEMM: 25 x 32 = 800 tiles, covering M=2000 with zero padded FLOPs
    dim3 grid(N_OUT / BN, T_STEPS / BM);   // (32, 25)
    gemm_nt_kernel<<<grid, 320>>>(x, weight, lif_ptr, N_IN);

    // Scan: 128 CTAs x 1 warp (unchanged R8)
    lif_scan_kernel<<<128, 32>>>(lif_ptr, out,
                                 v_th, v_rest, v_reset, t_ref, tau);
}

// round 12
// speedup vs baseline: 1.1405x; 1.0718x over previous
#include <cuda_runtime.h>

#define T_STEPS 2000
#define N_IN    8192
#define N_OUT   4096

// 32 MB scratch for lif_input = x @ W^T  (allocation-free: __device__ global)
__device__ float g_lif[(size_t)T_STEPS * N_OUT];

// ---------------------------------------------------------------------------
// Phase 1: fp32 GEMM — R1's exact 128x128/BK=8/8x8 shape and math, plus
// double-buffered smem (1 barrier/iter) and register-staged LDG prefetch.
// Per-output ascending-k fma chain unchanged -> bit-exact vs reference.
// ---------------------------------------------------------------------------
constexpr int BM = 128, BN = 128, BK = 8, TM = 8, TN = 8;

__global__ __launch_bounds__(256, 2)
void gemm_nt_kernel(const float* __restrict__ A,   // [M,K]
                    const float* __restrict__ B,   // [N,K]
                    float* __restrict__ C,         // [M,N]
                    int M, int N, int K)
{
    __shared__ float As[2][BK][BM];   // 8 KB
    __shared__ float Bs[2][BK][BN];   // 8 KB

    const int tid = threadIdx.x;
    const int bm  = blockIdx.y * BM;
    const int bn  = blockIdx.x * BN;

    const int loadRow = tid >> 1;         // 0..127
    const int loadCol = (tid & 1) * 4;    // 0 or 4

    const int tr = (tid >> 4) * TM;       // 0..120
    const int tc = (tid & 15) * TN;       // 0..120

    float acc[TM][TN];
    #pragma unroll
    for (int i = 0; i < TM; i++)
        #pragma unroll
        for (int j = 0; j < TN; j++)
            acc[i][j] = 0.0f;

    const bool aValid = (bm + loadRow) < M;
    const float* Aptr = A + (size_t)(bm + loadRow) * K + loadCol;
    const float* Bptr = B + (size_t)(bn + loadRow) * K + loadCol;

    // stage chunk 0 in registers
    float4 a4 = aValid ? *(const float4*)(Aptr)
                       : make_float4(0.f, 0.f, 0.f, 0.f);
    float4 b4 = *(const float4*)(Bptr);

    int s = 0;
    for (int k0 = 0; k0 < K; k0 += BK) {
        // commit staged registers to smem buffer s
        As[s][loadCol + 0][loadRow] = a4.x;
        As[s][loadCol + 1][loadRow] = a4.y;
        As[s][loadCol + 2][loadRow] = a4.z;
        As[s][loadCol + 3][loadRow] = a4.w;
        Bs[s][loadCol + 0][loadRow] = b4.x;
        Bs[s][loadCol + 1][loadRow] = b4.y;
        Bs[s][loadCol + 2][loadRow] = b4.z;
        Bs[s][loadCol + 3][loadRow] = b4.w;
        __syncthreads();                       // single barrier per iteration

        // issue next chunk's LDG; latency hidden under the compute below
        if (k0 + BK < K) {
            a4 = aValid ? *(const float4*)(Aptr + k0 + BK)
                        : make_float4(0.f, 0.f, 0.f, 0.f);
            b4 = *(const float4*)(Bptr + k0 + BK);
        }

        #pragma unroll
        for (int k = 0; k < BK; k++) {
            float ar[TM], br[TN];
            #pragma unroll
            for (int i = 0; i < TM; i++) ar[i] = As[s][k][tr + i];
            #pragma unroll
            for (int j = 0; j < TN; j++) br[j] = Bs[s][k][tc + j];
            #pragma unroll
            for (int i = 0; i < TM; i++)
                #pragma unroll
                for (int j = 0; j < TN; j++)
                    acc[i][j] += ar[i] * br[j];   // ascending-k fma chain
        }
        s ^= 1;
    }

    #pragma unroll
    for (int i = 0; i < TM; i++) {
        int gm = bm + tr + i;
        if (gm < M) {
            float* Crow = C + (size_t)gm * N + bn + tc;
            #pragma unroll
            for (int j = 0; j < TN; j += 4) {
                float4 v = make_float4(acc[i][j], acc[i][j+1],
                                       acc[i][j+2], acc[i][j+3]);
                *(float4*)(Crow + j) = v;
            }
        }
    }
}

// ---------------------------------------------------------------------------
// Phase 2: LIF scan — unchanged from R8 (91 us, rel_err 0.0)
// ---------------------------------------------------------------------------
constexpr int PF = 16;          // 1999 = 16 (prime) + 123*16 + 15 (tail)
constexpr int NBATCH = 123;
constexpr int TAIL = 15;

__device__ __forceinline__ float lif_step(float inp, float& v, float& refrac,
                                          float dt_tau, float rest, float th,
                                          float rst, float trf)
{
    const float DT = 0.001f;
    float v1 = v - dt_tau * (v - rest);
    float va = v1 + inp;
    v1 = (refrac == 0.0f) ? va : v1;
    float rf = refrac - DT;
    rf = (refrac > 0.0f) ? rf : 0.0f;
    float spike = (v1 - th >= 0.0f) ? 1.0f : 0.0f;
    bool sb = (spike > 0.0f);
    refrac = sb ? trf : rf;
    v = sb ? rst : v1;
    return spike;
}

__global__ __launch_bounds__(32)
void lif_scan_kernel(const float* __restrict__ lif,
                     float* __restrict__ out,
                     const float* __restrict__ v_th,
                     const float* __restrict__ v_rest,
                     const float* __restrict__ v_reset,
                     const float* __restrict__ t_ref,
                     const float* __restrict__ tau)
{
    const int n = blockIdx.x * 32 + threadIdx.x;

    const float th   = v_th[n];
    const float rest = v_rest[n];
    const float rst  = v_reset[n];
    const float trf  = t_ref[n];
    const float dt_tau = 0.001f * tau[n];

    float v = rest;
    float refrac = 0.0f;
    out[n] = 0.0f;

    const float* p = lif + (size_t)1 * N_OUT + n;
    float*       q = out + (size_t)1 * N_OUT + n;

    float buf[PF];
    #pragma unroll
    for (int j = 0; j < PF; j++) buf[j] = p[(size_t)j * N_OUT];
    p += (size_t)PF * N_OUT;

    for (int b = 0; b < NBATCH; b++) {
        float cur[PF];
        #pragma unroll
        for (int j = 0; j < PF; j++) cur[j] = buf[j];
        #pragma unroll
        for (int j = 0; j < PF; j++) buf[j] = p[(size_t)j * N_OUT];
        p += (size_t)PF * N_OUT;
        #pragma unroll
        for (int j = 0; j < PF; j++)
            q[(size_t)j * N_OUT] =
                lif_step(cur[j], v, refrac, dt_tau, rest, th, rst, trf);
        q += (size_t)PF * N_OUT;
    }

    {
        float tail[TAIL];
        #pragma unroll
        for (int j = 0; j < TAIL; j++) tail[j] = p[(size_t)j * N_OUT];
        #pragma unroll
        for (int j = 0; j < PF; j++)
            q[(size_t)j * N_OUT] =
                lif_step(buf[j], v, refrac, dt_tau, rest, th, rst, trf);
        q += (size_t)PF * N_OUT;
        #pragma unroll
        for (int j = 0; j < TAIL; j++)
            q[(size_t)j * N_OUT] =
                lif_step(tail[j], v, refrac, dt_tau, rest, th, rst, trf);
    }
}

// ---------------------------------------------------------------------------
extern "C" void kernel_launch(void* const* d_in, const int* in_sizes, int n_in,
                              void* d_out, int out_size)
{
    const float* x       = (const float*)d_in[0];  // [T, N_IN]
    const float* weight  = (const float*)d_in[1];  // [N_OUT, N_IN]
    const float* v_th    = (const float*)d_in[2];
    const float* v_rest  = (const float*)d_in[3];
    const float* v_reset = (const float*)d_in[4];
    const float* t_ref   = (const float*)d_in[5];
    const float* tau     = (const float*)d_in[6];
    float* out = (float*)d_out;                    // [T, N_OUT]

    float* lif_ptr = nullptr;
    cudaGetSymbolAddress((void**)&lif_ptr, g_lif);

    // GEMM: R1 shape (16 x 32 tiles of 128x128), double-buffered pipeline
    dim3 grid(N_OUT / BN, (T_STEPS + BM - 1) / BM);
    gemm_nt_kernel<<<grid, 256>>>(x, weight, lif_ptr, T_STEPS, N_OUT, N_IN);

    // Scan: 128 CTAs x 1 warp (unchanged R8)
    lif_scan_kernel<<<128, 32>>>(lif_ptr, out,
                                 v_th, v_rest, v_reset, t_ref, tau);
}

// round 13
// speedup vs baseline: 1.1538x; 1.0117x over previous
#include <cuda_runtime.h>

#define T_STEPS 2000
#define N_IN    8192
#define N_OUT   4096

__device__ float g_lif[(size_t)T_STEPS * N_OUT];
__device__ int   g_flags[16];

constexpr int BM = 128, BN = 128, BK = 8, TM = 8, TN = 8;
constexpr int M_BLK = 16, N_BLK = 32;

__global__ void zero_flags_kernel() {
    if (threadIdx.x < M_BLK) g_flags[threadIdx.x] = 0;
}

__device__ __forceinline__ int ld_acquire_gpu(const int* p) {
    int v;
    asm volatile("ld.acquire.gpu.s32 %0, [%1];" : "=r"(v) : "l"(p) : "memory");
    return v;
}

// ---------------------------------------------------------------------------
// GEMM — R12's double-buffered kernel, math byte-identical (ascending-k fp32
// fma chain per output). Only addition: per-m-block completion flag.
// ---------------------------------------------------------------------------
__global__ __launch_bounds__(256, 2)
void gemm_nt_kernel(const float* __restrict__ A,
                    const float* __restrict__ B,
                    float* __restrict__ C,
                    int M, int N, int K)
{
    __shared__ float As[2][BK][BM];
    __shared__ float Bs[2][BK][BN];

    const int tid = threadIdx.x;
    const int bm  = blockIdx.y * BM;
    const int bn  = blockIdx.x * BN;

    const int loadRow = tid >> 1;
    const int loadCol = (tid & 1) * 4;
    const int tr = (tid >> 4) * TM;
    const int tc = (tid & 15) * TN;

    float acc[TM][TN];
    #pragma unroll
    for (int i = 0; i < TM; i++)
        #pragma unroll
        for (int j = 0; j < TN; j++)
            acc[i][j] = 0.0f;

    const bool aValid = (bm + loadRow) < M;
    const float* Aptr = A + (size_t)(bm + loadRow) * K + loadCol;
    const float* Bptr = B + (size_t)(bn + loadRow) * K + loadCol;

    float4 a4 = aValid ? *(const float4*)(Aptr) : make_float4(0.f, 0.f, 0.f, 0.f);
    float4 b4 = *(const float4*)(Bptr);

    int s = 0;
    for (int k0 = 0; k0 < K; k0 += BK) {
        As[s][loadCol + 0][loadRow] = a4.x;
        As[s][loadCol + 1][loadRow] = a4.y;
        As[s][loadCol + 2][loadRow] = a4.z;
        As[s][loadCol + 3][loadRow] = a4.w;
        Bs[s][loadCol + 0][loadRow] = b4.x;
        Bs[s][loadCol + 1][loadRow] = b4.y;
        Bs[s][loadCol + 2][loadRow] = b4.z;
        Bs[s][loadCol + 3][loadRow] = b4.w;
        __syncthreads();

        if (k0 + BK < K) {
            a4 = aValid ? *(const float4*)(Aptr + k0 + BK)
                        : make_float4(0.f, 0.f, 0.f, 0.f);
            b4 = *(const float4*)(Bptr + k0 + BK);
        }

        #pragma unroll
        for (int k = 0; k < BK; k++) {
            float ar[TM], br[TN];
            #pragma unroll
            for (int i = 0; i < TM; i++) ar[i] = As[s][k][tr + i];
            #pragma unroll
            for (int j = 0; j < TN; j++) br[j] = Bs[s][k][tc + j];
            #pragma unroll
            for (int i = 0; i < TM; i++)
                #pragma unroll
                for (int j = 0; j < TN; j++)
                    acc[i][j] += ar[i] * br[j];
        }
        s ^= 1;
    }

    #pragma unroll
    for (int i = 0; i < TM; i++) {
        int gm = bm + tr + i;
        if (gm < M) {
            float* Crow = C + (size_t)gm * N + bn + tc;
            #pragma unroll
            for (int j = 0; j < TN; j += 4) {
                float4 v = make_float4(acc[i][j], acc[i][j+1],
                                       acc[i][j+2], acc[i][j+3]);
                *(float4*)(Crow + j) = v;
            }
        }
    }

    __threadfence();
    __syncthreads();
    if (tid == 0) atomicAdd(&g_flags[blockIdx.y], 1);
}

// ---------------------------------------------------------------------------
// LIF scan — value-identical to the rel_err-0.0 form; one FSETP drives all
// selects (v1>=th  <=>  v1-th>=0;  spike>0  <=>  same predicate).
// ---------------------------------------------------------------------------
__device__ __forceinline__ float lif_step(float inp, float& v, float& refrac,
                                          float dt_tau, float rest, float th,
                                          float rst, float trf)
{
    const float DT = 0.001f;
    float v1 = v - dt_tau * (v - rest);
    float va = v1 + inp;
    v1 = (refrac == 0.0f) ? va : v1;
    float rf = refrac - DT;
    rf = (refrac > 0.0f) ? rf : 0.0f;
    bool p = (v1 >= th);                 // == (v1 - th >= 0)
    float spike = p ? 1.0f : 0.0f;
    refrac = p ? trf : rf;
    v = p ? rst : v1;
    return spike;
}

__global__ __launch_bounds__(32)
void lif_scan_kernel(const float* __restrict__ lif,
                     float* __restrict__ out,
                     const float* __restrict__ v_th,
                     const float* __restrict__ v_rest,
                     const float* __restrict__ v_reset,
                     const float* __restrict__ t_ref,
                     const float* __restrict__ tau)
{
    const int n = blockIdx.x * 32 + threadIdx.x;   // 128*32 = 4096

    const float th   = v_th[n];
    const float rest = v_rest[n];
    const float rst  = v_reset[n];
    const float trf  = t_ref[n];
    const float dt_tau = 0.001f * tau[n];

    float v = rest;
    float refrac = 0.0f;
    out[n] = 0.0f;

    for (int b = 0; b < M_BLK; b++) {
        const int t0 = (b == 0) ? 1 : b * BM;
        const int t1 = (b + 1) * BM < T_STEPS ? (b + 1) * BM : T_STEPS;

        // wait for all 32 n-tiles of m-block b (all lanes poll same word)
        while (ld_acquire_gpu(&g_flags[b]) < N_BLK) __nanosleep(128);
        __syncwarp();

        int t = t0;
        while (t + 16 <= t1) {
            float buf[16];
            #pragma unroll
            for (int j = 0; j < 16; j++)
                buf[j] = lif[(size_t)(t + j) * N_OUT + n];
            #pragma unroll
            for (int j = 0; j < 16; j++)
                out[(size_t)(t + j) * N_OUT + n] =
                    lif_step(buf[j], v, refrac, dt_tau, rest, th, rst, trf);
            t += 16;
        }
        while (t < t1) {
            float inp = lif[(size_t)t * N_OUT + n];
            out[(size_t)t * N_OUT + n] =
                lif_step(inp, v, refrac, dt_tau, rest, th, rst, trf);
            t++;
        }
    }
}

// ---------------------------------------------------------------------------
extern "C" void kernel_launch(void* const* d_in, const int* in_sizes, int n_in,
                              void* d_out, int out_size)
{
    const float* x       = (const float*)d_in[0];
    const float* weight  = (const float*)d_in[1];
    const float* v_th    = (const float*)d_in[2];
    const float* v_rest  = (const float*)d_in[3];
    const float* v_reset = (const float*)d_in[4];
    const float* t_ref   = (const float*)d_in[5];
    const float* tau     = (const float*)d_in[6];
    float* out = (float*)d_out;

    float* lif_ptr = nullptr;
    cudaGetSymbolAddress((void**)&lif_ptr, g_lif);

    // fork resources (created per call; a handful of calls total, no device mem)
    cudaStream_t s2;
    cudaEvent_t ev0, ev1;
    cudaStreamCreateWithFlags(&s2, cudaStreamNonBlocking);
    cudaEventCreateWithFlags(&ev0, cudaEventDisableTiming);
    cudaEventCreateWithFlags(&ev1, cudaEventDisableTiming);

    // main stream: reset flags, then fork
    zero_flags_kernel<<<1, 32>>>();
    cudaEventRecord(ev0, 0);
    cudaStreamWaitEvent(s2, ev0, 0);

    // branch A (main stream): GEMM producer
    dim3 grid(N_OUT / BN, (T_STEPS + BM - 1) / BM);
    gemm_nt_kernel<<<grid, 256>>>(x, weight, lif_ptr, T_STEPS, N_OUT, N_IN);

    // branch B (s2): scan consumer, polls per-m-block flags
    lif_scan_kernel<<<128, 32, 0, s2>>>(lif_ptr, out,
                                        v_th, v_rest, v_reset, t_ref, tau);

    // join
    cudaEventRecord(ev1, s2);
    cudaStreamWaitEvent(0, ev1, 0);
}